// round 17
// baseline (speedup 1.0000x reference)
#include <cuda_runtime.h>
#include <cuda_bf16.h>

// CRF NLL: B=1024, T=512, K=64, START=62, STOP=63
// Tensor-core formulation: warp processes 8 similar-length sequences.
// Step: D(64x8,f32) = Et(64x64,bf16) @ V(64x8,bf16) via 16x mma.m16n8k16,
// then per-column w = D * exp(emit) (masked past each column's length),
// per-column power-of-2 rescale every 4 steps, pack bf16 -> SMEM ->
// ldmatrix.x4.trans rebuilds B fragments. Et A-fragments register-resident.
// 128 CTAs x 32 threads (1 warp/SM). Sorted grouping via order_kernel.

#define B_ 1024
#define T_ 512
#define K_ 64
#define START_ 62
#define STOP_ 63

typedef unsigned int u32;

__device__ int g_order[B_];

__device__ __forceinline__ u32 bf2pack(float lo, float hi) {
    __nv_bfloat162 h = __floats2bfloat162_rn(lo, hi);
    return *reinterpret_cast<u32*>(&h);
}

// Rank batches by descending length; zero the output accumulator.
__global__ void order_kernel(const int* __restrict__ lengths, float* out) {
    __shared__ int L[B_];
    const int tid = threadIdx.x;                 // 256 threads, grid 4
    for (int j = tid; j < B_; j += 256) L[j] = lengths[j];
    __syncthreads();
    const int b = blockIdx.x * 256 + tid;
    const int mylen = L[b];
    int rank = 0;
    for (int j = 0; j < B_; ++j) {
        int lj = L[j];
        rank += (lj > mylen) || (lj == mylen && j < b);
    }
    g_order[rank] = b;
    if (b == 0) out[0] = 0.0f;
}

__device__ __forceinline__ void mma16816(float d[4], const u32 a[4],
                                         u32 b0, u32 b1) {
    asm volatile(
        "mma.sync.aligned.m16n8k16.row.col.f32.bf16.bf16.f32 "
        "{%0,%1,%2,%3}, {%4,%5,%6,%7}, {%8,%9}, {%0,%1,%2,%3};"
        : "+f"(d[0]), "+f"(d[1]), "+f"(d[2]), "+f"(d[3])
        : "r"(a[0]), "r"(a[1]), "r"(a[2]), "r"(a[3]), "r"(b0), "r"(b1));
}

__global__ void __launch_bounds__(32, 1) crf_mma(
    const float* __restrict__ feats,      // [B,T,K]
    const int*   __restrict__ lengths,    // [B]
    const int*   __restrict__ tags,       // [B,T]
    const float* __restrict__ trans,      // [K,K] trans[next, prev]
    float* __restrict__ out)
{
    __shared__ __align__(16) u32 V[64 * 4];   // 64 rows x 8 bf16 (16B/row)

    const int lane = threadIdx.x;
    const int g    = blockIdx.x;              // group of 8 sequences
    const int grp  = lane & 3;                // column-pair group
    const int r0   = lane >> 2;               // base row (D/A row = r0 + 8m)
    const int c0   = 2 * grp, c1 = c0 + 1;    // owned columns (sequences)

    const int sA = g_order[8 * g + c0];
    const int sB = g_order[8 * g + c1];
    const int lenA = lengths[sA], lenB = lengths[sB];
    const int lenMax = lengths[g_order[8 * g]];   // descending order

    // ---- A fragments: Et = exp(trans), 4 M-tiles x 4 K-tiles, m16n8k16 ----
    // a0:(i0, j0,j0+1) a1:(i0+8,..) a2:(i0, j0+8,j0+9) a3:(i0+8, j0+8..)
    u32 Af[4][4][4];
#pragma unroll
    for (int mt = 0; mt < 4; ++mt)
#pragma unroll
        for (int kt = 0; kt < 4; ++kt) {
            const int i0 = 16 * mt + r0, j0 = 16 * kt + c0;
            Af[mt][kt][0] = bf2pack(__expf(trans[i0 * K_ + j0]),
                                    __expf(trans[i0 * K_ + j0 + 1]));
            Af[mt][kt][1] = bf2pack(__expf(trans[(i0 + 8) * K_ + j0]),
                                    __expf(trans[(i0 + 8) * K_ + j0 + 1]));
            Af[mt][kt][2] = bf2pack(__expf(trans[i0 * K_ + j0 + 8]),
                                    __expf(trans[i0 * K_ + j0 + 9]));
            Af[mt][kt][3] = bf2pack(__expf(trans[(i0 + 8) * K_ + j0 + 8]),
                                    __expf(trans[(i0 + 8) * K_ + j0 + 9]));
        }
    float EtS[8];
#pragma unroll
    for (int m = 0; m < 8; ++m)
        EtS[m] = __expf(trans[STOP_ * K_ + r0 + 8 * m]);

    // ---- gold scores, one sequence at a time, full-warp parallel over t ----
    float goldc0 = 0.f, goldc1 = 0.f;
    for (int s8 = 0; s8 < 8; ++s8) {
        const int b = g_order[8 * g + s8];
        const int len = lengths[b];
        const float* fb = feats + (size_t)b * (T_ * K_);
        const int*   tb = tags  + (size_t)b * T_;
        float gold = 0.f;
#pragma unroll
        for (int q = 0; q < 16; ++q) {
            int t = lane + 32 * q;
            if (t < len) {
                int tg = tb[t];
                int pv = t ? tb[t - 1] : START_;
                gold += fb[t * K_ + tg] + trans[tg * K_ + pv];
            }
        }
        if (lane == 0) gold += trans[STOP_ * K_ + tb[len - 1]];
#pragma unroll
        for (int off = 16; off; off >>= 1)
            gold += __shfl_xor_sync(0xFFFFFFFFu, gold, off);
        if (grp == (s8 >> 1)) { if (s8 & 1) goldc1 = gold; else goldc0 = gold; }
    }

    // ---- V0: 1.0 at START row, all 8 columns ----
#pragma unroll
    for (int k = lane; k < 256; k += 32)
        V[k] = ((k >> 2) == START_) ? 0x3F803F80u : 0u;
    __syncwarp();

    const u32 vbase   = (u32)__cvta_generic_to_shared(V);
    const u32 ldsm_a0 = vbase + lane * 16;          // rows 0..31  (ktiles 0,1)
    const u32 ldsm_a1 = vbase + (32 + lane) * 16;   // rows 32..63 (ktiles 2,3)

    const float* pA = feats + (size_t)sA * (T_ * K_) + r0;
    const float* pB = feats + (size_t)sB * (T_ * K_) + r0;

    float rawA[8], rawB[8];
#pragma unroll
    for (int m = 0; m < 8; ++m) { rawA[m] = pA[8 * m]; rawB[m] = pB[8 * m]; }

    int ktA = 0, ktB = 0;
    float uA = 0.f, uB = 0.f;

    for (int t = 0; t < lenMax; ++t) {
        // ---- rebuild B fragments from SMEM (trans -> .col layout) ----
        u32 b0, b1, b2, b3, b4, b5, b6, b7;
        asm volatile(
            "ldmatrix.sync.aligned.m8n8.x4.trans.shared.b16 {%0,%1,%2,%3}, [%4];"
            : "=r"(b0), "=r"(b1), "=r"(b2), "=r"(b3) : "r"(ldsm_a0) : "memory");
        asm volatile(
            "ldmatrix.sync.aligned.m8n8.x4.trans.shared.b16 {%0,%1,%2,%3}, [%4];"
            : "=r"(b4), "=r"(b5), "=r"(b6), "=r"(b7) : "r"(ldsm_a1) : "memory");
        const u32 bb0[4] = {b0, b2, b4, b6};
        const u32 bb1[4] = {b1, b3, b5, b7};

        // ---- emission exps for this step (masked past column length) ----
        const bool liveA = t < lenA, liveB = t < lenB;
        float eA[8], eB[8];
#pragma unroll
        for (int m = 0; m < 8; ++m) {
            eA[m] = liveA ? __expf(rawA[m]) : 0.f;
            eB[m] = liveB ? __expf(rawB[m]) : 0.f;
        }
        // prefetch next step's raw emissions (clamped; garbage masked later)
        {
            const int tn = min(t + 1, T_ - 1);
#pragma unroll
            for (int m = 0; m < 8; ++m) {
                rawA[m] = pA[tn * K_ + 8 * m];
                rawB[m] = pB[tn * K_ + 8 * m];
            }
        }

        // ---- D = Et @ V : 16 mma, k-outer for chain interleave ----
        float d[4][4];
#pragma unroll
        for (int mt = 0; mt < 4; ++mt)
#pragma unroll
            for (int rg = 0; rg < 4; ++rg) d[mt][rg] = 0.f;
#pragma unroll
        for (int kt = 0; kt < 4; ++kt)
#pragma unroll
            for (int mt = 0; mt < 4; ++mt)
                mma16816(d[mt], Af[mt][kt], bb0[kt], bb1[kt]);

        // ---- apply emissions: d rows r0+8m; reg0/2 -> col c0, reg1/3 -> c1 --
#pragma unroll
        for (int mt = 0; mt < 4; ++mt) {
            d[mt][0] *= eA[2 * mt];
            d[mt][1] *= eB[2 * mt];
            d[mt][2] *= eA[2 * mt + 1];
            d[mt][3] *= eB[2 * mt + 1];
        }

        // ---- per-column power-of-2 rescale every 4 steps ----
        if ((t & 3) == 3) {
            float mA = 0.f, mB = 0.f;
#pragma unroll
            for (int mt = 0; mt < 4; ++mt) {
                mA = fmaxf(mA, fmaxf(d[mt][0], d[mt][2]));
                mB = fmaxf(mB, fmaxf(d[mt][1], d[mt][3]));
            }
#pragma unroll
            for (int off = 4; off <= 16; off <<= 1) {   // reduce over l/4
                mA = fmaxf(mA, __shfl_xor_sync(0xFFFFFFFFu, mA, off));
                mB = fmaxf(mB, __shfl_xor_sync(0xFFFFFFFFu, mB, off));
            }
            if (mA > 0.f) {
                int k = ((__float_as_int(mA) >> 23) & 0xFF) - 127;
                ktA += k;
                float sc = __int_as_float((127 - k) << 23);
#pragma unroll
                for (int mt = 0; mt < 4; ++mt) { d[mt][0] *= sc; d[mt][2] *= sc; }
            }
            if (mB > 0.f) {
                int k = ((__float_as_int(mB) >> 23) & 0xFF) - 127;
                ktB += k;
                float sc = __int_as_float((127 - k) << 23);
#pragma unroll
                for (int mt = 0; mt < 4; ++mt) { d[mt][1] *= sc; d[mt][3] *= sc; }
            }
        }

        // ---- terminal capture when a column reaches its length ----
        if (__any_sync(0xFFFFFFFFu, (t + 1 == lenA) || (t + 1 == lenB))) {
            float pAa = 0.f, pBa = 0.f;
#pragma unroll
            for (int mt = 0; mt < 4; ++mt) {
                pAa += d[mt][0] * EtS[2 * mt] + d[mt][2] * EtS[2 * mt + 1];
                pBa += d[mt][1] * EtS[2 * mt] + d[mt][3] * EtS[2 * mt + 1];
            }
#pragma unroll
            for (int off = 4; off <= 16; off <<= 1) {
                pAa += __shfl_xor_sync(0xFFFFFFFFu, pAa, off);
                pBa += __shfl_xor_sync(0xFFFFFFFFu, pBa, off);
            }
            if (t + 1 == lenA) uA = pAa;   // ktA frozen after: column goes 0
            if (t + 1 == lenB) uB = pBa;
        }

        // ---- pack bf16 and store V for next step ----
#pragma unroll
        for (int mt = 0; mt < 4; ++mt) {
            V[(16 * mt + r0) * 4 + grp]     = bf2pack(d[mt][0], d[mt][1]);
            V[(16 * mt + 8 + r0) * 4 + grp] = bf2pack(d[mt][2], d[mt][3]);
        }
        __syncwarp();
    }

    // ---- finalize: lanes 0..3 own column pairs (0,1),(2,3),(4,6),(6,7) ----
    float res = 0.f;
    if (lane < 4) {
        const double LN2 = 0.69314718055994530942;
        float fwdA = (float)((double)ktA * LN2) + logf(uA);
        float fwdB = (float)((double)ktB * LN2) + logf(uB);
        res = (fwdA - goldc0) + (fwdB - goldc1);
    }
    res += __shfl_xor_sync(0xFFFFFFFFu, res, 1);
    res += __shfl_xor_sync(0xFFFFFFFFu, res, 2);
    if (lane == 0) atomicAdd(out, res * (1.0f / (float)B_));
}

extern "C" void kernel_launch(void* const* d_in, const int* in_sizes, int n_in,
                              void* d_out, int out_size)
{
    const float* feats   = (const float*)d_in[0];
    const int*   lengths = (const int*)  d_in[1];
    const int*   tags    = (const int*)  d_in[2];
    const float* trans   = (const float*)d_in[3];
    float* out = (float*)d_out;

    order_kernel<<<4, 256>>>(lengths, out);
    crf_mma<<<B_ / 8, 32>>>(feats, lengths, tags, trans, out);
}